// round 1
// baseline (speedup 1.0000x reference)
#include <cuda_runtime.h>
#include <cuda_bf16.h>
#include <math.h>
#include <stdint.h>

// ---------------- problem constants ----------------
#define EDIM 4096
#define NH   32
#define HD   128
#define Lseq 8192          // 8*32*32
#define Bb   2
#define VD   1536
#define NQ   64
#define NROWS (Bb*Lseq)    // 16384

// ---------------- scratch (device globals; no allocations) ----------------
__device__ float g_cos[Lseq * 2048];
__device__ float g_sin[Lseq * 2048];
__device__ float g_kv[NROWS * EDIM];      // post-LN kv, (b*L+l, E)
__device__ float g_kvrot[NROWS * EDIM];
__device__ float g_kp[NROWS * EDIM];
__device__ float g_vp[NROWS * EDIM];
__device__ float g_scores[(size_t)Bb * NH * NQ * Lseq];  // ((b*32+h)*64+q, L)
__device__ float g_qn[NQ * EDIM];
__device__ float g_qp[NQ * EDIM];
__device__ float g_ctx[Bb * NQ * EDIM];   // row = b*64+q
__device__ float g_out1[Bb * NQ * EDIM];
__device__ float g_ln2[Bb * NQ * EDIM];

// ---------------- RoPE cos/sin table ----------------
// freqs layout: [f_t(512) f_t(512) f_h(768) f_h(768) f_w(768) f_w(768)], take even idx j=2i
__global__ void rope_table_kernel(float* __restrict__ ct, float* __restrict__ st) {
    int l = blockIdx.x;                // 0..8191
    int t = l >> 10;                   // /1024
    int rem = l & 1023;
    float hh = (float)(rem >> 5);
    float ww = (float)(rem & 31);
    // t position with interpolation + clip at table end (max_t=24 -> clip 23)
    float pos = (float)t * (10.0f / 3.0f);
    float lo = floorf(pos); if (lo > 23.f) lo = 23.f;
    float hi = ceilf(pos);  if (hi > 23.f) hi = 23.f;
    float w  = pos - lo;
    float pt = lo * (1.f - w) + hi * w;

    size_t base = (size_t)l * 2048;
    for (int i = threadIdx.x; i < 2048; i += 256) {
        int j = 2 * i;
        float theta;
        if (j < 1024) {
            int k = j & 511;
            theta = pt * powf(10000.f, -(float)(2 * k) / 1024.f);
        } else if (j < 2560) {
            int k = (j - 1024) % 768;
            theta = hh * powf(10000.f, -(float)(2 * k) / 1536.f);
        } else {
            int k = (j - 2560) % 768;
            theta = ww * powf(10000.f, -(float)(2 * k) / 1536.f);
        }
        ct[base + i] = cosf(theta);
        st[base + i] = sinf(theta);
    }
}

// ---------------- LayerNorm over 4096 cols ----------------
__global__ void ln_kernel(const float* __restrict__ in, float* __restrict__ out,
                          const float* __restrict__ w, const float* __restrict__ b) {
    __shared__ __align__(16) float row[4096];
    __shared__ float red[256];
    size_t base = (size_t)blockIdx.x * 4096;
    int tid = threadIdx.x;
    float s = 0.f;
    for (int i = tid; i < 4096; i += 256) { float v = in[base + i]; row[i] = v; s += v; }
    red[tid] = s; __syncthreads();
    for (int off = 128; off > 0; off >>= 1) {
        if (tid < off) red[tid] += red[tid + off];
        __syncthreads();
    }
    float mean = red[0] * (1.f / 4096.f);
    __syncthreads();
    float vs = 0.f;
    for (int i = tid; i < 4096; i += 256) { float d = row[i] - mean; vs += d * d; }
    red[tid] = vs; __syncthreads();
    for (int off = 128; off > 0; off >>= 1) {
        if (tid < off) red[tid] += red[tid + off];
        __syncthreads();
    }
    float inv = rsqrtf(red[0] * (1.f / 4096.f) + 1e-6f);
    for (int i = tid; i < 4096; i += 256)
        out[base + i] = (row[i] - mean) * inv * w[i] + b[i];
}

// ---------------- RoPE apply ----------------
__global__ void rope_kernel(const float* __restrict__ kv,
                            const float* __restrict__ ct, const float* __restrict__ st,
                            float* __restrict__ outp) {
    int r = blockIdx.x;        // b*L + l
    int l = r & (Lseq - 1);
    const float2* x = (const float2*)(kv + (size_t)r * EDIM);
    float2* y = (float2*)(outp + (size_t)r * EDIM);
    const float* c = ct + (size_t)l * 2048;
    const float* s = st + (size_t)l * 2048;
    for (int i = threadIdx.x; i < 2048; i += 256) {
        float2 v = x[i];
        float cc = c[i], ss = s[i];
        float2 o;
        o.x = v.x * cc - v.y * ss;
        o.y = v.x * ss + v.y * cc;
        y[i] = o;
    }
}

// ---------------- GEMM: C = alpha*(A . B^T) + bias   (A: MxK lda, B: NxK ldb) ----------------
__global__ __launch_bounds__(256)
void gemm_tn(const float* __restrict__ A, int lda,
             const float* __restrict__ B, int ldb,
             float* __restrict__ C, int ldc,
             int M, int N, int K,
             const float* __restrict__ bias, float alpha) {
    __shared__ __align__(16) float As[8][128];
    __shared__ __align__(16) float Bs[8][128];
    int tid = threadIdx.x;
    int m0 = blockIdx.y * 128, n0 = blockIdx.x * 128;
    int arow = tid >> 1;
    int acol = (tid & 1) * 4;
    int ty = tid >> 4, tx = tid & 15;

    float acc[8][8];
#pragma unroll
    for (int i = 0; i < 8; i++)
#pragma unroll
        for (int j = 0; j < 8; j++) acc[i][j] = 0.f;

    for (int k0 = 0; k0 < K; k0 += 8) {
        float4 av = make_float4(0.f, 0.f, 0.f, 0.f);
        int gm = m0 + arow;
        if (gm < M) av = *(const float4*)&A[(size_t)gm * lda + k0 + acol];
        As[acol + 0][arow] = av.x; As[acol + 1][arow] = av.y;
        As[acol + 2][arow] = av.z; As[acol + 3][arow] = av.w;
        float4 bv = make_float4(0.f, 0.f, 0.f, 0.f);
        int gn = n0 + arow;
        if (gn < N) bv = *(const float4*)&B[(size_t)gn * ldb + k0 + acol];
        Bs[acol + 0][arow] = bv.x; Bs[acol + 1][arow] = bv.y;
        Bs[acol + 2][arow] = bv.z; Bs[acol + 3][arow] = bv.w;
        __syncthreads();
#pragma unroll
        for (int kk = 0; kk < 8; kk++) {
            float4 a0 = *(const float4*)&As[kk][ty * 8];
            float4 a1 = *(const float4*)&As[kk][ty * 8 + 4];
            float4 b0 = *(const float4*)&Bs[kk][tx * 8];
            float4 b1 = *(const float4*)&Bs[kk][tx * 8 + 4];
            float a[8] = {a0.x, a0.y, a0.z, a0.w, a1.x, a1.y, a1.z, a1.w};
            float bb[8] = {b0.x, b0.y, b0.z, b0.w, b1.x, b1.y, b1.z, b1.w};
#pragma unroll
            for (int i = 0; i < 8; i++)
#pragma unroll
                for (int j = 0; j < 8; j++)
                    acc[i][j] = fmaf(a[i], bb[j], acc[i][j]);
        }
        __syncthreads();
    }
#pragma unroll
    for (int i = 0; i < 8; i++) {
        int gm = m0 + ty * 8 + i;
        if (gm >= M) continue;
#pragma unroll
        for (int j = 0; j < 8; j++) {
            int gn = n0 + tx * 8 + j;
            if (gn >= N) continue;
            float v = acc[i][j] * alpha;
            if (bias) v += bias[gn];
            C[(size_t)gm * ldc + gn] = v;
        }
    }
}

// ---------------- GEMM: C = A . B   (A: MxK lda, B: KxN ldb) ----------------
__global__ __launch_bounds__(256)
void gemm_nn(const float* __restrict__ A, int lda,
             const float* __restrict__ B, int ldb,
             float* __restrict__ C, int ldc,
             int M, int N, int K) {
    __shared__ __align__(16) float As[8][128];
    __shared__ __align__(16) float Bs[8][128];
    int tid = threadIdx.x;
    int m0 = blockIdx.y * 128, n0 = blockIdx.x * 128;
    int arow = tid >> 1;
    int acol = (tid & 1) * 4;
    int bkr = tid >> 5;            // 0..7
    int bnc = (tid & 31) * 4;      // 0..124
    int ty = tid >> 4, tx = tid & 15;

    float acc[8][8];
#pragma unroll
    for (int i = 0; i < 8; i++)
#pragma unroll
        for (int j = 0; j < 8; j++) acc[i][j] = 0.f;

    for (int k0 = 0; k0 < K; k0 += 8) {
        float4 av = make_float4(0.f, 0.f, 0.f, 0.f);
        int gm = m0 + arow;
        if (gm < M) av = *(const float4*)&A[(size_t)gm * lda + k0 + acol];
        As[acol + 0][arow] = av.x; As[acol + 1][arow] = av.y;
        As[acol + 2][arow] = av.z; As[acol + 3][arow] = av.w;
        float4 bv = make_float4(0.f, 0.f, 0.f, 0.f);
        int gn = n0 + bnc;
        if (gn < N) bv = *(const float4*)&B[(size_t)(k0 + bkr) * ldb + gn];
        *(float4*)&Bs[bkr][bnc] = bv;
        __syncthreads();
#pragma unroll
        for (int kk = 0; kk < 8; kk++) {
            float4 a0 = *(const float4*)&As[kk][ty * 8];
            float4 a1 = *(const float4*)&As[kk][ty * 8 + 4];
            float4 b0 = *(const float4*)&Bs[kk][tx * 8];
            float4 b1 = *(const float4*)&Bs[kk][tx * 8 + 4];
            float a[8] = {a0.x, a0.y, a0.z, a0.w, a1.x, a1.y, a1.z, a1.w};
            float bb[8] = {b0.x, b0.y, b0.z, b0.w, b1.x, b1.y, b1.z, b1.w};
#pragma unroll
            for (int i = 0; i < 8; i++)
#pragma unroll
                for (int j = 0; j < 8; j++)
                    acc[i][j] = fmaf(a[i], bb[j], acc[i][j]);
        }
        __syncthreads();
    }
#pragma unroll
    for (int i = 0; i < 8; i++) {
        int gm = m0 + ty * 8 + i;
        if (gm >= M) continue;
#pragma unroll
        for (int j = 0; j < 8; j++) {
            int gn = n0 + tx * 8 + j;
            if (gn >= N) continue;
            C[(size_t)gm * ldc + gn] = acc[i][j];
        }
    }
}

// ---------------- scores: S[b,h,q,k] = qp[q,h,:].kp[b*L+k,h,:] / sqrt(128) ----------------
__global__ __launch_bounds__(256)
void scores_kernel(const float* __restrict__ qp, const float* __restrict__ kp,
                   float* __restrict__ scores) {
    int kt = blockIdx.x;   // key tile (64 keys)
    int h = blockIdx.y;
    int b = blockIdx.z;
    __shared__ __align__(16) float Qs[16][64];
    __shared__ __align__(16) float Ks[16][64];
    int tid = threadIdx.x;
    int ty = tid >> 4, tx = tid & 15;
    float acc[4][4];
#pragma unroll
    for (int i = 0; i < 4; i++)
#pragma unroll
        for (int j = 0; j < 4; j++) acc[i][j] = 0.f;

    const float* qbase = qp + h * HD;
    const float* kbase = kp + ((size_t)b * Lseq + kt * 64) * EDIM + h * HD;
    int r = tid >> 2;          // 0..63
    int c = (tid & 3) * 4;     // 0..12

    for (int d0 = 0; d0 < HD; d0 += 16) {
        float4 qv = *(const float4*)&qbase[(size_t)r * EDIM + d0 + c];
        Qs[c + 0][r] = qv.x; Qs[c + 1][r] = qv.y; Qs[c + 2][r] = qv.z; Qs[c + 3][r] = qv.w;
        float4 kv4 = *(const float4*)&kbase[(size_t)r * EDIM + d0 + c];
        Ks[c + 0][r] = kv4.x; Ks[c + 1][r] = kv4.y; Ks[c + 2][r] = kv4.z; Ks[c + 3][r] = kv4.w;
        __syncthreads();
#pragma unroll
        for (int dd = 0; dd < 16; dd++) {
            float4 a = *(const float4*)&Qs[dd][ty * 4];
            float4 bb = *(const float4*)&Ks[dd][tx * 4];
            float av[4] = {a.x, a.y, a.z, a.w};
            float bv[4] = {bb.x, bb.y, bb.z, bb.w};
#pragma unroll
            for (int i = 0; i < 4; i++)
#pragma unroll
                for (int j = 0; j < 4; j++)
                    acc[i][j] = fmaf(av[i], bv[j], acc[i][j]);
        }
        __syncthreads();
    }
    const float sc = 0.08838834764831845f;  // 1/sqrt(128)
    size_t base = ((size_t)(b * NH + h) * NQ) * Lseq;
#pragma unroll
    for (int i = 0; i < 4; i++)
#pragma unroll
        for (int j = 0; j < 4; j++)
            scores[base + (size_t)(ty * 4 + i) * Lseq + kt * 64 + tx * 4 + j] = acc[i][j] * sc;
}

// ---------------- softmax over L=8192 per row ----------------
__global__ void softmax_kernel(float* __restrict__ s) {
    float* p = s + (size_t)blockIdx.x * Lseq;
    int tid = threadIdx.x;
    __shared__ float red[256];
    float mx = -1e30f;
    for (int i = tid; i < Lseq; i += 256) mx = fmaxf(mx, p[i]);
    red[tid] = mx; __syncthreads();
    for (int off = 128; off > 0; off >>= 1) {
        if (tid < off) red[tid] = fmaxf(red[tid], red[tid + off]);
        __syncthreads();
    }
    mx = red[0];
    __syncthreads();
    float sum = 0.f;
    for (int i = tid; i < Lseq; i += 256) {
        float e = expf(p[i] - mx);
        p[i] = e;
        sum += e;
    }
    red[tid] = sum; __syncthreads();
    for (int off = 128; off > 0; off >>= 1) {
        if (tid < off) red[tid] += red[tid + off];
        __syncthreads();
    }
    float inv = 1.f / red[0];
    __syncthreads();
    for (int i = tid; i < Lseq; i += 256) p[i] *= inv;
}

// ---------------- ctx: split-K over keys, atomic accumulate ----------------
__global__ __launch_bounds__(256)
void ctx_kernel(const float* __restrict__ attn, const float* __restrict__ vp,
                float* __restrict__ ctx) {
    int ks = blockIdx.x;   // 0..7, 1024 keys each
    int h = blockIdx.y;
    int b = blockIdx.z;
    __shared__ __align__(16) float As[16][64];
    __shared__ __align__(16) float Vs[16][128];
    int tid = threadIdx.x;
    int qy = tid >> 4, dx = tid & 15;
    float acc[4][8];
#pragma unroll
    for (int i = 0; i < 4; i++)
#pragma unroll
        for (int j = 0; j < 8; j++) acc[i][j] = 0.f;

    int r = tid >> 2;          // 0..63 (q)
    int c = (tid & 3) * 4;     // 0..12 (k)
    int vr = tid >> 5;         // 0..7
    int vc = (tid & 31) * 4;   // 0..124
    size_t arow = (size_t)(b * NH + h) * NQ;

    for (int kc = 0; kc < 1024; kc += 16) {
        int kglob = ks * 1024 + kc;
        float4 av = *(const float4*)&attn[(arow + r) * Lseq + kglob + c];
        As[c + 0][r] = av.x; As[c + 1][r] = av.y; As[c + 2][r] = av.z; As[c + 3][r] = av.w;
#pragma unroll
        for (int p = 0; p < 2; p++) {
            int row = p * 8 + vr;
            float4 vv = *(const float4*)&vp[((size_t)(b * Lseq + kglob + row)) * EDIM + h * HD + vc];
            *(float4*)&Vs[row][vc] = vv;
        }
        __syncthreads();
#pragma unroll
        for (int kk = 0; kk < 16; kk++) {
            float4 a = *(const float4*)&As[kk][qy * 4];
            float av4[4] = {a.x, a.y, a.z, a.w};
            float4 v0 = *(const float4*)&Vs[kk][dx * 8];
            float4 v1 = *(const float4*)&Vs[kk][dx * 8 + 4];
            float vv[8] = {v0.x, v0.y, v0.z, v0.w, v1.x, v1.y, v1.z, v1.w};
#pragma unroll
            for (int i = 0; i < 4; i++)
#pragma unroll
                for (int j = 0; j < 8; j++)
                    acc[i][j] = fmaf(av4[i], vv[j], acc[i][j]);
        }
        __syncthreads();
    }
#pragma unroll
    for (int i = 0; i < 4; i++) {
        int q = qy * 4 + i;
#pragma unroll
        for (int j = 0; j < 8; j++)
            atomicAdd(&ctx[((size_t)(b * NQ + q)) * EDIM + h * HD + dx * 8 + j], acc[i][j]);
    }
}

// ---------------- launch ----------------
extern "C" void kernel_launch(void* const* d_in, const int* in_sizes, int n_in,
                              void* d_out, int out_size) {
    const float* cube      = (const float*)d_in[0];
    const float* query     = (const float*)d_in[1];
    const float* kv_proj_w = (const float*)d_in[2];
    const float* ln_q_w    = (const float*)d_in[3];
    const float* ln_q_b    = (const float*)d_in[4];
    const float* ln_kv_w   = (const float*)d_in[5];
    const float* ln_kv_b   = (const float*)d_in[6];
    const float* ln_post_w = (const float*)d_in[7];
    const float* ln_post_b = (const float*)d_in[8];
    const float* in_proj_w = (const float*)d_in[9];
    const float* in_proj_b = (const float*)d_in[10];
    const float* out_proj_w= (const float*)d_in[11];
    const float* out_proj_b= (const float*)d_in[12];
    const float* proj      = (const float*)d_in[13];
    float* out = (float*)d_out;

    float *cosT, *sinT, *kv, *kvrot, *kp, *vp, *scores, *qn, *qp, *ctx, *out1, *ln2;
    cudaGetSymbolAddress((void**)&cosT,  g_cos);
    cudaGetSymbolAddress((void**)&sinT,  g_sin);
    cudaGetSymbolAddress((void**)&kv,    g_kv);
    cudaGetSymbolAddress((void**)&kvrot, g_kvrot);
    cudaGetSymbolAddress((void**)&kp,    g_kp);
    cudaGetSymbolAddress((void**)&vp,    g_vp);
    cudaGetSymbolAddress((void**)&scores,g_scores);
    cudaGetSymbolAddress((void**)&qn,    g_qn);
    cudaGetSymbolAddress((void**)&qp,    g_qp);
    cudaGetSymbolAddress((void**)&ctx,   g_ctx);
    cudaGetSymbolAddress((void**)&out1,  g_out1);
    cudaGetSymbolAddress((void**)&ln2,   g_ln2);

    const size_t EE = (size_t)EDIM * EDIM;

    // RoPE tables
    rope_table_kernel<<<Lseq, 256>>>(cosT, sinT);

    // kv = cube @ kv_proj_w^T ; LN ; RoPE
    gemm_tn<<<dim3(EDIM / 128, NROWS / 128), 256>>>(cube, VD, kv_proj_w, VD,
                                                    kv, EDIM, NROWS, EDIM, VD, nullptr, 1.f);
    ln_kernel<<<NROWS, 256>>>(kv, kv, ln_kv_w, ln_kv_b);
    rope_kernel<<<NROWS, 256>>>(kv, cosT, sinT, kvrot);

    // kp = kv_rot @ Wk^T + bk ; vp = kv @ Wv^T + bv
    gemm_tn<<<dim3(EDIM / 128, NROWS / 128), 256>>>(kvrot, EDIM, in_proj_w + EE, EDIM,
                                                    kp, EDIM, NROWS, EDIM, EDIM,
                                                    in_proj_b + EDIM, 1.f);
    gemm_tn<<<dim3(EDIM / 128, NROWS / 128), 256>>>(kv, EDIM, in_proj_w + 2 * EE, EDIM,
                                                    vp, EDIM, NROWS, EDIM, EDIM,
                                                    in_proj_b + 2 * EDIM, 1.f);

    // q path
    ln_kernel<<<NQ, 256>>>(query, qn, ln_q_w, ln_q_b);
    gemm_tn<<<dim3(EDIM / 128, 1), 256>>>(qn, EDIM, in_proj_w, EDIM,
                                          qp, EDIM, NQ, EDIM, EDIM, in_proj_b, 1.f);

    // attention
    scores_kernel<<<dim3(Lseq / 64, NH, Bb), 256>>>(qp, kp, scores);
    softmax_kernel<<<Bb * NH * NQ, 256>>>(scores);
    cudaMemsetAsync(ctx, 0, (size_t)Bb * NQ * EDIM * sizeof(float), 0);
    ctx_kernel<<<dim3(8, NH, Bb), 256>>>(scores, vp, ctx);

    // out proj + post LN + final proj
    gemm_tn<<<dim3(EDIM / 128, 1), 256>>>(ctx, EDIM, out_proj_w, EDIM,
                                          out1, EDIM, Bb * NQ, EDIM, EDIM, out_proj_b, 1.f);
    ln_kernel<<<Bb * NQ, 256>>>(out1, ln2, ln_post_w, ln_post_b);
    gemm_nn<<<dim3(EDIM / 128, 1), 256>>>(ln2, EDIM, proj, EDIM,
                                          out, EDIM, Bb * NQ, EDIM, EDIM);
}

// round 2
// speedup vs baseline: 2.0747x; 2.0747x over previous
#include <cuda_runtime.h>
#include <cuda_bf16.h>
#include <math.h>
#include <stdint.h>

// ---------------- problem constants ----------------
#define EDIM 4096
#define NH   32
#define HD   128
#define Lseq 8192          // 8*32*32
#define Bb   2
#define VD   1536
#define NQ   64
#define NROWS (Bb*Lseq)    // 16384

// ---------------- scratch (device globals; no allocations) ----------------
__device__ float g_kv[NROWS * EDIM];      // post-LN kv, (b*L+l, E)
__device__ float g_kvrot[NROWS * EDIM];
__device__ float g_kp[NROWS * EDIM];
__device__ float g_vp[NROWS * EDIM];
__device__ float g_scores[(size_t)Bb * NH * NQ * Lseq];  // ((b*32+h)*64+q, L)
__device__ float g_qn[NQ * EDIM];
__device__ float g_qp[NQ * EDIM];
__device__ float g_ctx[Bb * NQ * EDIM];   // row = b*64+q
__device__ float g_out1[Bb * NQ * EDIM];
__device__ float g_ln2[Bb * NQ * EDIM];

// ---------------- tf32 helpers ----------------
__device__ __forceinline__ uint32_t f2tf32(float x) {
    uint32_t r;
    asm("cvt.rna.tf32.f32 %0, %1;" : "=r"(r) : "f"(x));
    return r;
}

__device__ __forceinline__ void mma_tf32(float c[4],
                                         uint32_t a0, uint32_t a1, uint32_t a2, uint32_t a3,
                                         uint32_t b0, uint32_t b1) {
    asm("mma.sync.aligned.m16n8k8.row.col.f32.tf32.tf32.f32 "
        "{%0,%1,%2,%3}, {%4,%5,%6,%7}, {%8,%9}, {%0,%1,%2,%3};"
        : "+f"(c[0]), "+f"(c[1]), "+f"(c[2]), "+f"(c[3])
        : "r"(a0), "r"(a1), "r"(a2), "r"(a3), "r"(b0), "r"(b1));
}

// ---------------- tf32 GEMM: C = A . B^T + bias ----------------
// A: MxK row-major (lda), B: NxK row-major (ldb). Requires M%128==0, N%128==0, K%16==0.
#define TSTR 136  // smem row stride (floats): 136 % 32 == 8 -> conflict-free frag loads
__global__ __launch_bounds__(256)
void gemm_tn_tf32(const float* __restrict__ A, int lda,
                  const float* __restrict__ B, int ldb,
                  float* __restrict__ C, int ldc,
                  int M, int N, int K, const float* __restrict__ bias) {
    __shared__ uint32_t As[2][16 * TSTR];
    __shared__ uint32_t Bs[2][16 * TSTR];

    int tid = threadIdx.x;
    int lane = tid & 31;
    int wid = tid >> 5;
    int wm = (wid & 1) * 64;       // warp m offset within block
    int wn = (wid >> 1) * 32;      // warp n offset within block
    int m0 = blockIdx.y * 128, n0 = blockIdx.x * 128;

    int r    = tid >> 1;           // 0..127 (tile row)
    int koff = (tid & 1) * 8;      // 0 or 8

    const float* pA = A + (size_t)(m0 + r) * lda + koff;
    const float* pB = B + (size_t)(n0 + r) * ldb + koff;

    float acc[4][4][4];
#pragma unroll
    for (int i = 0; i < 4; i++)
#pragma unroll
        for (int j = 0; j < 4; j++)
#pragma unroll
            for (int t = 0; t < 4; t++) acc[i][j][t] = 0.f;

    // preload first tile
    {
        float4 a0 = *(const float4*)(pA);
        float4 a1 = *(const float4*)(pA + 4);
        float4 b0 = *(const float4*)(pB);
        float4 b1 = *(const float4*)(pB + 4);
        As[0][(koff + 0) * TSTR + r] = f2tf32(a0.x);
        As[0][(koff + 1) * TSTR + r] = f2tf32(a0.y);
        As[0][(koff + 2) * TSTR + r] = f2tf32(a0.z);
        As[0][(koff + 3) * TSTR + r] = f2tf32(a0.w);
        As[0][(koff + 4) * TSTR + r] = f2tf32(a1.x);
        As[0][(koff + 5) * TSTR + r] = f2tf32(a1.y);
        As[0][(koff + 6) * TSTR + r] = f2tf32(a1.z);
        As[0][(koff + 7) * TSTR + r] = f2tf32(a1.w);
        Bs[0][(koff + 0) * TSTR + r] = f2tf32(b0.x);
        Bs[0][(koff + 1) * TSTR + r] = f2tf32(b0.y);
        Bs[0][(koff + 2) * TSTR + r] = f2tf32(b0.z);
        Bs[0][(koff + 3) * TSTR + r] = f2tf32(b0.w);
        Bs[0][(koff + 4) * TSTR + r] = f2tf32(b1.x);
        Bs[0][(koff + 5) * TSTR + r] = f2tf32(b1.y);
        Bs[0][(koff + 6) * TSTR + r] = f2tf32(b1.z);
        Bs[0][(koff + 7) * TSTR + r] = f2tf32(b1.w);
    }
    __syncthreads();

    int buf = 0;
    for (int k0 = 0; k0 < K; k0 += 16) {
        bool last = (k0 + 16 >= K);
        float4 pa0, pa1, pb0, pb1;
        if (!last) {
            const float* qA = pA + k0 + 16;
            const float* qB = pB + k0 + 16;
            pa0 = *(const float4*)(qA);
            pa1 = *(const float4*)(qA + 4);
            pb0 = *(const float4*)(qB);
            pb1 = *(const float4*)(qB + 4);
        }

        const uint32_t* as = As[buf];
        const uint32_t* bs = Bs[buf];
#pragma unroll
        for (int kk = 0; kk < 16; kk += 8) {
            int kr = kk + (lane & 3);
            int mrow = wm + (lane >> 2);
            int ncol = wn + (lane >> 2);
            uint32_t af[4][4], bf[4][2];
#pragma unroll
            for (int i = 0; i < 4; i++) {
                af[i][0] = as[kr * TSTR + mrow + i * 16];
                af[i][1] = as[kr * TSTR + mrow + i * 16 + 8];
                af[i][2] = as[(kr + 4) * TSTR + mrow + i * 16];
                af[i][3] = as[(kr + 4) * TSTR + mrow + i * 16 + 8];
            }
#pragma unroll
            for (int j = 0; j < 4; j++) {
                bf[j][0] = bs[kr * TSTR + ncol + j * 8];
                bf[j][1] = bs[(kr + 4) * TSTR + ncol + j * 8];
            }
#pragma unroll
            for (int i = 0; i < 4; i++)
#pragma unroll
                for (int j = 0; j < 4; j++)
                    mma_tf32(acc[i][j], af[i][0], af[i][1], af[i][2], af[i][3],
                             bf[j][0], bf[j][1]);
        }

        if (!last) {
            int nb = buf ^ 1;
            As[nb][(koff + 0) * TSTR + r] = f2tf32(pa0.x);
            As[nb][(koff + 1) * TSTR + r] = f2tf32(pa0.y);
            As[nb][(koff + 2) * TSTR + r] = f2tf32(pa0.z);
            As[nb][(koff + 3) * TSTR + r] = f2tf32(pa0.w);
            As[nb][(koff + 4) * TSTR + r] = f2tf32(pa1.x);
            As[nb][(koff + 5) * TSTR + r] = f2tf32(pa1.y);
            As[nb][(koff + 6) * TSTR + r] = f2tf32(pa1.z);
            As[nb][(koff + 7) * TSTR + r] = f2tf32(pa1.w);
            Bs[nb][(koff + 0) * TSTR + r] = f2tf32(pb0.x);
            Bs[nb][(koff + 1) * TSTR + r] = f2tf32(pb0.y);
            Bs[nb][(koff + 2) * TSTR + r] = f2tf32(pb0.z);
            Bs[nb][(koff + 3) * TSTR + r] = f2tf32(pb0.w);
            Bs[nb][(koff + 4) * TSTR + r] = f2tf32(pb1.x);
            Bs[nb][(koff + 5) * TSTR + r] = f2tf32(pb1.y);
            Bs[nb][(koff + 6) * TSTR + r] = f2tf32(pb1.z);
            Bs[nb][(koff + 7) * TSTR + r] = f2tf32(pb1.w);
            __syncthreads();
            buf = nb;
        }
    }

    // epilogue
#pragma unroll
    for (int j = 0; j < 4; j++) {
        int col = n0 + wn + j * 8 + (lane & 3) * 2;
        float b0v = bias ? bias[col] : 0.f;
        float b1v = bias ? bias[col + 1] : 0.f;
#pragma unroll
        for (int i = 0; i < 4; i++) {
            int row = m0 + wm + i * 16 + (lane >> 2);
            float2 v0 = make_float2(acc[i][j][0] + b0v, acc[i][j][1] + b1v);
            float2 v1 = make_float2(acc[i][j][2] + b0v, acc[i][j][3] + b1v);
            *(float2*)&C[(size_t)row * ldc + col] = v0;
            *(float2*)&C[(size_t)(row + 8) * ldc + col] = v1;
        }
    }
}

// ---------------- fused LayerNorm + RoPE for kv (in-place LN + rotated copy) ----------------
__global__ void ln_rope_kernel(float* __restrict__ kv, float* __restrict__ kvrot,
                               const float* __restrict__ w, const float* __restrict__ b) {
    __shared__ __align__(16) float row[4096];
    __shared__ float red[256];
    int rix = blockIdx.x;            // b*L + l
    int l = rix & (Lseq - 1);
    size_t base = (size_t)rix * 4096;
    int tid = threadIdx.x;

    float s = 0.f;
    for (int i = tid; i < 4096; i += 256) { float v = kv[base + i]; row[i] = v; s += v; }
    red[tid] = s; __syncthreads();
    for (int off = 128; off > 0; off >>= 1) {
        if (tid < off) red[tid] += red[tid + off];
        __syncthreads();
    }
    float mean = red[0] * (1.f / 4096.f);
    __syncthreads();
    float vs = 0.f;
    for (int i = tid; i < 4096; i += 256) { float d = row[i] - mean; vs += d * d; }
    red[tid] = vs; __syncthreads();
    for (int off = 128; off > 0; off >>= 1) {
        if (tid < off) red[tid] += red[tid + off];
        __syncthreads();
    }
    float inv = rsqrtf(red[0] * (1.f / 4096.f) + 1e-6f);
    __syncthreads();

    // position values
    int t = l >> 10;
    int rem = l & 1023;
    float hh = (float)(rem >> 5);
    float ww = (float)(rem & 31);
    float pos = (float)t * (10.0f / 3.0f);
    float lo = floorf(pos); if (lo > 23.f) lo = 23.f;
    float hi = ceilf(pos);  if (hi > 23.f) hi = 23.f;
    float wgt = pos - lo;
    float pt = lo * (1.f - wgt) + hi * wgt;

    for (int i = tid; i < 2048; i += 256) {
        int j = 2 * i;
        float x1 = (row[j] - mean) * inv * w[j] + b[j];
        float x2 = (row[j + 1] - mean) * inv * w[j + 1] + b[j + 1];
        float theta;
        if (j < 1024) {
            int k = j & 511;
            theta = pt * powf(10000.f, -(float)(2 * k) / 1024.f);
        } else if (j < 2560) {
            int k = (j - 1024) % 768;
            theta = hh * powf(10000.f, -(float)(2 * k) / 1536.f);
        } else {
            int k = (j - 2560) % 768;
            theta = ww * powf(10000.f, -(float)(2 * k) / 1536.f);
        }
        float cc = cosf(theta), ss = sinf(theta);
        kv[base + j]     = x1;
        kv[base + j + 1] = x2;
        kvrot[base + j]     = x1 * cc - x2 * ss;
        kvrot[base + j + 1] = x1 * ss + x2 * cc;
    }
}

// ---------------- plain LayerNorm over 4096 cols (small row counts) ----------------
__global__ void ln_kernel(const float* __restrict__ in, float* __restrict__ out,
                          const float* __restrict__ w, const float* __restrict__ b) {
    __shared__ __align__(16) float row[4096];
    __shared__ float red[256];
    size_t base = (size_t)blockIdx.x * 4096;
    int tid = threadIdx.x;
    float s = 0.f;
    for (int i = tid; i < 4096; i += 256) { float v = in[base + i]; row[i] = v; s += v; }
    red[tid] = s; __syncthreads();
    for (int off = 128; off > 0; off >>= 1) {
        if (tid < off) red[tid] += red[tid + off];
        __syncthreads();
    }
    float mean = red[0] * (1.f / 4096.f);
    __syncthreads();
    float vs = 0.f;
    for (int i = tid; i < 4096; i += 256) { float d = row[i] - mean; vs += d * d; }
    red[tid] = vs; __syncthreads();
    for (int off = 128; off > 0; off >>= 1) {
        if (tid < off) red[tid] += red[tid + off];
        __syncthreads();
    }
    float inv = rsqrtf(red[0] * (1.f / 4096.f) + 1e-6f);
    for (int i = tid; i < 4096; i += 256)
        out[base + i] = (row[i] - mean) * inv * w[i] + b[i];
}

// ---------------- fp32 GEMM: C = A . B^T + bias (small M) ----------------
__global__ __launch_bounds__(256)
void gemm_tn(const float* __restrict__ A, int lda,
             const float* __restrict__ B, int ldb,
             float* __restrict__ C, int ldc,
             int M, int N, int K,
             const float* __restrict__ bias, float alpha) {
    __shared__ __align__(16) float As[8][128];
    __shared__ __align__(16) float Bs[8][128];
    int tid = threadIdx.x;
    int m0 = blockIdx.y * 128, n0 = blockIdx.x * 128;
    int arow = tid >> 1;
    int acol = (tid & 1) * 4;
    int ty = tid >> 4, tx = tid & 15;

    float acc[8][8];
#pragma unroll
    for (int i = 0; i < 8; i++)
#pragma unroll
        for (int j = 0; j < 8; j++) acc[i][j] = 0.f;

    for (int k0 = 0; k0 < K; k0 += 8) {
        float4 av = make_float4(0.f, 0.f, 0.f, 0.f);
        int gm = m0 + arow;
        if (gm < M) av = *(const float4*)&A[(size_t)gm * lda + k0 + acol];
        As[acol + 0][arow] = av.x; As[acol + 1][arow] = av.y;
        As[acol + 2][arow] = av.z; As[acol + 3][arow] = av.w;
        float4 bv = make_float4(0.f, 0.f, 0.f, 0.f);
        int gn = n0 + arow;
        if (gn < N) bv = *(const float4*)&B[(size_t)gn * ldb + k0 + acol];
        Bs[acol + 0][arow] = bv.x; Bs[acol + 1][arow] = bv.y;
        Bs[acol + 2][arow] = bv.z; Bs[acol + 3][arow] = bv.w;
        __syncthreads();
#pragma unroll
        for (int kk = 0; kk < 8; kk++) {
            float4 a0 = *(const float4*)&As[kk][ty * 8];
            float4 a1 = *(const float4*)&As[kk][ty * 8 + 4];
            float4 b0 = *(const float4*)&Bs[kk][tx * 8];
            float4 b1 = *(const float4*)&Bs[kk][tx * 8 + 4];
            float a[8] = {a0.x, a0.y, a0.z, a0.w, a1.x, a1.y, a1.z, a1.w};
            float bb[8] = {b0.x, b0.y, b0.z, b0.w, b1.x, b1.y, b1.z, b1.w};
#pragma unroll
            for (int i = 0; i < 8; i++)
#pragma unroll
                for (int j = 0; j < 8; j++)
                    acc[i][j] = fmaf(a[i], bb[j], acc[i][j]);
        }
        __syncthreads();
    }
#pragma unroll
    for (int i = 0; i < 8; i++) {
        int gm = m0 + ty * 8 + i;
        if (gm >= M) continue;
#pragma unroll
        for (int j = 0; j < 8; j++) {
            int gn = n0 + tx * 8 + j;
            if (gn >= N) continue;
            float v = acc[i][j] * alpha;
            if (bias) v += bias[gn];
            C[(size_t)gm * ldc + gn] = v;
        }
    }
}

// ---------------- fp32 GEMM: C = A . B (small M) ----------------
__global__ __launch_bounds__(256)
void gemm_nn(const float* __restrict__ A, int lda,
             const float* __restrict__ B, int ldb,
             float* __restrict__ C, int ldc,
             int M, int N, int K) {
    __shared__ __align__(16) float As[8][128];
    __shared__ __align__(16) float Bs[8][128];
    int tid = threadIdx.x;
    int m0 = blockIdx.y * 128, n0 = blockIdx.x * 128;
    int arow = tid >> 1;
    int acol = (tid & 1) * 4;
    int bkr = tid >> 5;
    int bnc = (tid & 31) * 4;
    int ty = tid >> 4, tx = tid & 15;

    float acc[8][8];
#pragma unroll
    for (int i = 0; i < 8; i++)
#pragma unroll
        for (int j = 0; j < 8; j++) acc[i][j] = 0.f;

    for (int k0 = 0; k0 < K; k0 += 8) {
        float4 av = make_float4(0.f, 0.f, 0.f, 0.f);
        int gm = m0 + arow;
        if (gm < M) av = *(const float4*)&A[(size_t)gm * lda + k0 + acol];
        As[acol + 0][arow] = av.x; As[acol + 1][arow] = av.y;
        As[acol + 2][arow] = av.z; As[acol + 3][arow] = av.w;
        float4 bv = make_float4(0.f, 0.f, 0.f, 0.f);
        int gn = n0 + bnc;
        if (gn < N) bv = *(const float4*)&B[(size_t)(k0 + bkr) * ldb + gn];
        *(float4*)&Bs[bkr][bnc] = bv;
        __syncthreads();
#pragma unroll
        for (int kk = 0; kk < 8; kk++) {
            float4 a0 = *(const float4*)&As[kk][ty * 8];
            float4 a1 = *(const float4*)&As[kk][ty * 8 + 4];
            float4 b0 = *(const float4*)&Bs[kk][tx * 8];
            float4 b1 = *(const float4*)&Bs[kk][tx * 8 + 4];
            float a[8] = {a0.x, a0.y, a0.z, a0.w, a1.x, a1.y, a1.z, a1.w};
            float bb[8] = {b0.x, b0.y, b0.z, b0.w, b1.x, b1.y, b1.z, b1.w};
#pragma unroll
            for (int i = 0; i < 8; i++)
#pragma unroll
                for (int j = 0; j < 8; j++)
                    acc[i][j] = fmaf(a[i], bb[j], acc[i][j]);
        }
        __syncthreads();
    }
#pragma unroll
    for (int i = 0; i < 8; i++) {
        int gm = m0 + ty * 8 + i;
        if (gm >= M) continue;
#pragma unroll
        for (int j = 0; j < 8; j++) {
            int gn = n0 + tx * 8 + j;
            if (gn >= N) continue;
            C[(size_t)gm * ldc + gn] = acc[i][j];
        }
    }
}

// ---------------- scores ----------------
__global__ __launch_bounds__(256)
void scores_kernel(const float* __restrict__ qp, const float* __restrict__ kp,
                   float* __restrict__ scores) {
    int kt = blockIdx.x;
    int h = blockIdx.y;
    int b = blockIdx.z;
    __shared__ __align__(16) float Qs[16][64];
    __shared__ __align__(16) float Ks[16][64];
    int tid = threadIdx.x;
    int ty = tid >> 4, tx = tid & 15;
    float acc[4][4];
#pragma unroll
    for (int i = 0; i < 4; i++)
#pragma unroll
        for (int j = 0; j < 4; j++) acc[i][j] = 0.f;

    const float* qbase = qp + h * HD;
    const float* kbase = kp + ((size_t)b * Lseq + kt * 64) * EDIM + h * HD;
    int r = tid >> 2;
    int c = (tid & 3) * 4;

    for (int d0 = 0; d0 < HD; d0 += 16) {
        float4 qv = *(const float4*)&qbase[(size_t)r * EDIM + d0 + c];
        Qs[c + 0][r] = qv.x; Qs[c + 1][r] = qv.y; Qs[c + 2][r] = qv.z; Qs[c + 3][r] = qv.w;
        float4 kv4 = *(const float4*)&kbase[(size_t)r * EDIM + d0 + c];
        Ks[c + 0][r] = kv4.x; Ks[c + 1][r] = kv4.y; Ks[c + 2][r] = kv4.z; Ks[c + 3][r] = kv4.w;
        __syncthreads();
#pragma unroll
        for (int dd = 0; dd < 16; dd++) {
            float4 a = *(const float4*)&Qs[dd][ty * 4];
            float4 bb = *(const float4*)&Ks[dd][tx * 4];
            float av[4] = {a.x, a.y, a.z, a.w};
            float bv[4] = {bb.x, bb.y, bb.z, bb.w};
#pragma unroll
            for (int i = 0; i < 4; i++)
#pragma unroll
                for (int j = 0; j < 4; j++)
                    acc[i][j] = fmaf(av[i], bv[j], acc[i][j]);
        }
        __syncthreads();
    }
    const float sc = 0.08838834764831845f;
    size_t base = ((size_t)(b * NH + h) * NQ) * Lseq;
#pragma unroll
    for (int i = 0; i < 4; i++)
#pragma unroll
        for (int j = 0; j < 4; j++)
            scores[base + (size_t)(ty * 4 + i) * Lseq + kt * 64 + tx * 4 + j] = acc[i][j] * sc;
}

// ---------------- softmax ----------------
__global__ void softmax_kernel(float* __restrict__ s) {
    float* p = s + (size_t)blockIdx.x * Lseq;
    int tid = threadIdx.x;
    __shared__ float red[256];
    float mx = -1e30f;
    for (int i = tid; i < Lseq; i += 256) mx = fmaxf(mx, p[i]);
    red[tid] = mx; __syncthreads();
    for (int off = 128; off > 0; off >>= 1) {
        if (tid < off) red[tid] = fmaxf(red[tid], red[tid + off]);
        __syncthreads();
    }
    mx = red[0];
    __syncthreads();
    float sum = 0.f;
    for (int i = tid; i < Lseq; i += 256) {
        float e = expf(p[i] - mx);
        p[i] = e;
        sum += e;
    }
    red[tid] = sum; __syncthreads();
    for (int off = 128; off > 0; off >>= 1) {
        if (tid < off) red[tid] += red[tid + off];
        __syncthreads();
    }
    float inv = 1.f / red[0];
    __syncthreads();
    for (int i = tid; i < Lseq; i += 256) p[i] *= inv;
}

// ---------------- ctx ----------------
__global__ __launch_bounds__(256)
void ctx_kernel(const float* __restrict__ attn, const float* __restrict__ vp,
                float* __restrict__ ctx) {
    int ks = blockIdx.x;
    int h = blockIdx.y;
    int b = blockIdx.z;
    __shared__ __align__(16) float As[16][64];
    __shared__ __align__(16) float Vs[16][128];
    int tid = threadIdx.x;
    int qy = tid >> 4, dx = tid & 15;
    float acc[4][8];
#pragma unroll
    for (int i = 0; i < 4; i++)
#pragma unroll
        for (int j = 0; j < 8; j++) acc[i][j] = 0.f;

    int r = tid >> 2;
    int c = (tid & 3) * 4;
    int vr = tid >> 5;
    int vc = (tid & 31) * 4;
    size_t arow = (size_t)(b * NH + h) * NQ;

    for (int kc = 0; kc < 1024; kc += 16) {
        int kglob = ks * 1024 + kc;
        float4 av = *(const float4*)&attn[(arow + r) * Lseq + kglob + c];
        As[c + 0][r] = av.x; As[c + 1][r] = av.y; As[c + 2][r] = av.z; As[c + 3][r] = av.w;
#pragma unroll
        for (int p = 0; p < 2; p++) {
            int row = p * 8 + vr;
            float4 vv = *(const float4*)&vp[((size_t)(b * Lseq + kglob + row)) * EDIM + h * HD + vc];
            *(float4*)&Vs[row][vc] = vv;
        }
        __syncthreads();
#pragma unroll
        for (int kk = 0; kk < 16; kk++) {
            float4 a = *(const float4*)&As[kk][qy * 4];
            float av4[4] = {a.x, a.y, a.z, a.w};
            float4 v0 = *(const float4*)&Vs[kk][dx * 8];
            float4 v1 = *(const float4*)&Vs[kk][dx * 8 + 4];
            float vv[8] = {v0.x, v0.y, v0.z, v0.w, v1.x, v1.y, v1.z, v1.w};
#pragma unroll
            for (int i = 0; i < 4; i++)
#pragma unroll
                for (int j = 0; j < 8; j++)
                    acc[i][j] = fmaf(av4[i], vv[j], acc[i][j]);
        }
        __syncthreads();
    }
#pragma unroll
    for (int i = 0; i < 4; i++) {
        int q = qy * 4 + i;
#pragma unroll
        for (int j = 0; j < 8; j++)
            atomicAdd(&ctx[((size_t)(b * NQ + q)) * EDIM + h * HD + dx * 8 + j], acc[i][j]);
    }
}

// ---------------- launch ----------------
extern "C" void kernel_launch(void* const* d_in, const int* in_sizes, int n_in,
                              void* d_out, int out_size) {
    const float* cube      = (const float*)d_in[0];
    const float* query     = (const float*)d_in[1];
    const float* kv_proj_w = (const float*)d_in[2];
    const float* ln_q_w    = (const float*)d_in[3];
    const float* ln_q_b    = (const float*)d_in[4];
    const float* ln_kv_w   = (const float*)d_in[5];
    const float* ln_kv_b   = (const float*)d_in[6];
    const float* ln_post_w = (const float*)d_in[7];
    const float* ln_post_b = (const float*)d_in[8];
    const float* in_proj_w = (const float*)d_in[9];
    const float* in_proj_b = (const float*)d_in[10];
    const float* out_proj_w= (const float*)d_in[11];
    const float* out_proj_b= (const float*)d_in[12];
    const float* proj      = (const float*)d_in[13];
    float* out = (float*)d_out;

    float *kv, *kvrot, *kp, *vp, *scores, *qn, *qp, *ctx, *out1, *ln2;
    cudaGetSymbolAddress((void**)&kv,    g_kv);
    cudaGetSymbolAddress((void**)&kvrot, g_kvrot);
    cudaGetSymbolAddress((void**)&kp,    g_kp);
    cudaGetSymbolAddress((void**)&vp,    g_vp);
    cudaGetSymbolAddress((void**)&scores,g_scores);
    cudaGetSymbolAddress((void**)&qn,    g_qn);
    cudaGetSymbolAddress((void**)&qp,    g_qp);
    cudaGetSymbolAddress((void**)&ctx,   g_ctx);
    cudaGetSymbolAddress((void**)&out1,  g_out1);
    cudaGetSymbolAddress((void**)&ln2,   g_ln2);

    const size_t EE = (size_t)EDIM * EDIM;

    // kv = cube @ kv_proj_w^T (tf32 MMA) ; fused LN + RoPE
    gemm_tn_tf32<<<dim3(EDIM / 128, NROWS / 128), 256>>>(cube, VD, kv_proj_w, VD,
                                                         kv, EDIM, NROWS, EDIM, VD, nullptr);
    ln_rope_kernel<<<NROWS, 256>>>(kv, kvrot, ln_kv_w, ln_kv_b);

    // kp = kv_rot @ Wk^T + bk ; vp = kv @ Wv^T + bv (tf32 MMA)
    gemm_tn_tf32<<<dim3(EDIM / 128, NROWS / 128), 256>>>(kvrot, EDIM, in_proj_w + EE, EDIM,
                                                         kp, EDIM, NROWS, EDIM, EDIM,
                                                         in_proj_b + EDIM);
    gemm_tn_tf32<<<dim3(EDIM / 128, NROWS / 128), 256>>>(kv, EDIM, in_proj_w + 2 * EE, EDIM,
                                                         vp, EDIM, NROWS, EDIM, EDIM,
                                                         in_proj_b + 2 * EDIM);

    // q path (small, fp32)
    ln_kernel<<<NQ, 256>>>(query, qn, ln_q_w, ln_q_b);
    gemm_tn<<<dim3(EDIM / 128, 1), 256>>>(qn, EDIM, in_proj_w, EDIM,
                                          qp, EDIM, NQ, EDIM, EDIM, in_proj_b, 1.f);

    // attention
    scores_kernel<<<dim3(Lseq / 64, NH, Bb), 256>>>(qp, kp, scores);
    softmax_kernel<<<Bb * NH * NQ, 256>>>(scores);
    cudaMemsetAsync(ctx, 0, (size_t)Bb * NQ * EDIM * sizeof(float), 0);
    ctx_kernel<<<dim3(8, NH, Bb), 256>>>(scores, vp, ctx);

    // out proj + post LN + final proj (small, fp32)
    gemm_tn<<<dim3(EDIM / 128, 1), 256>>>(ctx, EDIM, out_proj_w, EDIM,
                                          out1, EDIM, Bb * NQ, EDIM, EDIM, out_proj_b, 1.f);
    ln_kernel<<<Bb * NQ, 256>>>(out1, ln2, ln_post_w, ln_post_b);
    gemm_nn<<<dim3(EDIM / 128, 1), 256>>>(ln2, EDIM, proj, EDIM,
                                          out, EDIM, Bb * NQ, EDIM, EDIM);
}